// round 14
// baseline (speedup 1.0000x reference)
#include <cuda_runtime.h>
#include <cuda_bf16.h>
#include <math.h>
#include <stdint.h>

// Problem constants
#define BB 2
#define SS 2048
#define DD 1024
#define HH 16
#define DHH 64
#define FF 4096
#define MM (BB * SS)   // 4096 rows total

// ---------------------------------------------------------------------------
// Scratch buffers (__device__ globals; no allocation allowed)
// ---------------------------------------------------------------------------
__device__ float g_q[(size_t)MM * DD];
__device__ float g_k[(size_t)MM * DD];
__device__ float g_v[(size_t)MM * DD];
__device__ float g_a[(size_t)MM * DD];
__device__ float g_t[(size_t)MM * DD];
__device__ float g_x[(size_t)MM * DD];
__device__ float g_y[(size_t)MM * DD];
__device__ float g_h[(size_t)MM * FF];
__device__ float g_wt[(size_t)16 * 1024 * 1024];  // transposed+rounded weights (64MB)
__device__ float g_dr[(size_t)MM * DD];   // rounded decoder input
__device__ float g_er[(size_t)MM * DD];   // rounded encoder output
__device__ float g_xr[(size_t)MM * DD];   // rounded x
__device__ float g_yr[(size_t)MM * DD];   // rounded y

// ---------------------------------------------------------------------------
// Helpers
// ---------------------------------------------------------------------------
__device__ __forceinline__ uint32_t f2tf32(float x)
{
    uint32_t r;
    asm("cvt.rna.tf32.f32 %0, %1;" : "=r"(r) : "f"(x));
    return r;
}

__device__ __forceinline__ float tf32r(float x)
{
    return __uint_as_float(f2tf32(x));
}

__device__ __forceinline__ uint32_t smem_u32(const void* p)
{
    uint32_t a;
    asm("{ .reg .u64 t; cvta.to.shared.u64 t, %1; cvt.u32.u64 %0, t; }"
        : "=r"(a) : "l"(p));
    return a;
}

__device__ __forceinline__ void cp16(uint32_t dst, const void* src)
{
    asm volatile("cp.async.cg.shared.global [%0], [%1], 16;"
                 :: "r"(dst), "l"(src));
}

#define CP_COMMIT()  asm volatile("cp.async.commit_group;" ::: "memory")
#define CP_WAIT(n)   asm volatile("cp.async.wait_group %0;" :: "n"(n) : "memory")

__device__ __forceinline__ void mma_tf32(float* c, const uint32_t* a, const uint32_t* b)
{
    asm volatile(
        "mma.sync.aligned.m16n8k8.row.col.f32.tf32.tf32.f32 "
        "{%0,%1,%2,%3}, {%4,%5,%6,%7}, {%8,%9}, {%0,%1,%2,%3};"
        : "+f"(c[0]), "+f"(c[1]), "+f"(c[2]), "+f"(c[3])
        : "r"(a[0]), "r"(a[1]), "r"(a[2]), "r"(a[3]), "r"(b[0]), "r"(b[1]));
}

__device__ __forceinline__ void ldsm4(uint32_t& r0, uint32_t& r1,
                                      uint32_t& r2, uint32_t& r3, uint32_t addr)
{
    asm volatile("ldmatrix.sync.aligned.m8n8.x4.shared.b16 {%0,%1,%2,%3}, [%4];"
                 : "=r"(r0), "=r"(r1), "=r"(r2), "=r"(r3) : "r"(addr));
}

// ---------------------------------------------------------------------------
// TF32 GEMM, cp.async 4-stage pipeline, ldmatrix operand loads.
// C[M,N] = A[M,K] @ WT[N,K]^T + bias[N]; A pre-rounded, WT pre-transposed+rounded.
// 128x128 CTA tile, BK=16, 256 threads (8 warps 2x4), warp tile 64x32.
// As: [4][128 m][20 k] floats, Bts: [4][128 n][20 k] floats.
// ---------------------------------------------------------------------------
#define ASTR 20
#define BTSTR 20
#define AWORDS (128 * ASTR)
#define BTWORDS (128 * BTSTR)
#define BBASE_W (4 * AWORDS)
#define GEMM_SMEM ((4 * AWORDS + 4 * BTWORDS) * 4)

__global__ __launch_bounds__(256)
void gemm_cp_kernel(const float* __restrict__ A, const float* __restrict__ WT,
                    const float* __restrict__ bias, float* __restrict__ C,
                    int M, int N, int K, int relu, int rnd)
{
    extern __shared__ float sm[];
    const uint32_t sb = smem_u32(sm);

    const int tid  = threadIdx.x;
    const int warp = tid >> 5;
    const int lane = tid & 31;
    const int wm   = warp >> 2;       // 0..1
    const int wn   = warp & 3;        // 0..3
    const int gid  = lane >> 2;       // 0..7
    const int tig  = lane & 3;        // 0..3

    const int bm = blockIdx.y * 128;
    const int bn = blockIdx.x * 128;

    // A loader: rows tid>>2 (+64), 16B chunk tid&3
    const int a_row = tid >> 2;
    const int a_c4  = tid & 3;
    // B loader: WT rows tid>>2 (+64), 16B chunk tid&3 (K-contiguous)
    const int b_row = tid >> 2;
    const int b_c4  = tid & 3;

    const float* Ag = A  + (size_t)(bm + a_row) * K + a_c4 * 4;
    const float* Wg = WT + (size_t)(bn + b_row) * K + b_c4 * 4;

    const uint32_t aoff0 = (uint32_t)((a_row * ASTR + a_c4 * 4) * 4);
    const uint32_t aoff1 = (uint32_t)(((a_row + 64) * ASTR + a_c4 * 4) * 4);
    const uint32_t boff0 = (uint32_t)((BBASE_W + b_row * BTSTR + b_c4 * 4) * 4);
    const uint32_t boff1 = (uint32_t)((BBASE_W + (b_row + 64) * BTSTR + b_c4 * 4) * 4);

    // per-lane ldmatrix offsets (bytes)
    const uint32_t a_lane4 =
        (uint32_t)((((lane & 7) + ((lane >> 3) & 1) * 8) * ASTR +
                    ((lane >> 4) & 1) * 4) * 4);
    const uint32_t b_lane4 =
        (uint32_t)((((lane & 7) + ((lane >> 4) & 1) * 8) * BTSTR +
                    ((lane >> 3) & 1) * 4) * 4);

    float acc[4][4][4];
#pragma unroll
    for (int i = 0; i < 4; i++)
#pragma unroll
        for (int j = 0; j < 4; j++)
#pragma unroll
            for (int r = 0; r < 4; r++) acc[i][j][r] = 0.f;

    const int T = K >> 4;

    // prologue: stages 0..2
#pragma unroll
    for (int s = 0; s < 3; s++) {
        const int k0 = s * 16;
        const uint32_t sa = sb + (uint32_t)(s * AWORDS * 4);
        const uint32_t sbb = sb + (uint32_t)(s * BTWORDS * 4);
        cp16(sa + aoff0, Ag + k0);
        cp16(sa + aoff1, Ag + (size_t)64 * K + k0);
        cp16(sbb + boff0, Wg + k0);
        cp16(sbb + boff1, Wg + (size_t)64 * K + k0);
        CP_COMMIT();
    }

    for (int it = 0; it < T; it++) {
        CP_WAIT(2);
        __syncthreads();

        const int st = it & 3;
        const uint32_t aw = st * AWORDS;
        const uint32_t bw = BBASE_W + st * BTWORDS;

#pragma unroll
        for (int kk = 0; kk < 2; kk++) {
            uint32_t af[4][4], bf[4][2];
            const int kb = kk * 8;
#pragma unroll
            for (int mt = 0; mt < 4; mt++) {
                uint32_t addr = sb + (uint32_t)((aw + (wm * 64 + mt * 16) * ASTR + kb) * 4)
                                + a_lane4;
                ldsm4(af[mt][0], af[mt][1], af[mt][2], af[mt][3], addr);
            }
#pragma unroll
            for (int p = 0; p < 2; p++) {
                uint32_t addr = sb + (uint32_t)((bw + (wn * 32 + p * 16) * BTSTR + kb) * 4)
                                + b_lane4;
                ldsm4(bf[2 * p][0], bf[2 * p][1], bf[2 * p + 1][0], bf[2 * p + 1][1], addr);
            }
#pragma unroll
            for (int mt = 0; mt < 4; mt++)
#pragma unroll
                for (int nt = 0; nt < 4; nt++)
                    mma_tf32(acc[mt][nt], af[mt], bf[nt]);
        }

        if (it + 3 < T) {
            const int ns = (it + 3) & 3;
            const int k0 = (it + 3) * 16;
            const uint32_t sa = sb + (uint32_t)(ns * AWORDS * 4);
            const uint32_t sbb = sb + (uint32_t)(ns * BTWORDS * 4);
            cp16(sa + aoff0, Ag + k0);
            cp16(sa + aoff1, Ag + (size_t)64 * K + k0);
            cp16(sbb + boff0, Wg + k0);
            cp16(sbb + boff1, Wg + (size_t)64 * K + k0);
        }
        CP_COMMIT();
    }

    // epilogue
#pragma unroll
    for (int mt = 0; mt < 4; mt++) {
        int row0 = bm + wm * 64 + mt * 16 + gid;
#pragma unroll
        for (int nt = 0; nt < 4; nt++) {
            int col = bn + wn * 32 + nt * 8 + tig * 2;
            float b0 = bias[col], b1 = bias[col + 1];
            float v0 = acc[mt][nt][0] + b0;
            float v1 = acc[mt][nt][1] + b1;
            float v2 = acc[mt][nt][2] + b0;
            float v3 = acc[mt][nt][3] + b1;
            if (relu) {
                v0 = fmaxf(v0, 0.f); v1 = fmaxf(v1, 0.f);
                v2 = fmaxf(v2, 0.f); v3 = fmaxf(v3, 0.f);
            }
            if (rnd) {
                v0 = tf32r(v0); v1 = tf32r(v1);
                v2 = tf32r(v2); v3 = tf32r(v3);
            }
            *(float2*)&C[(size_t)row0 * N + col]       = make_float2(v0, v1);
            *(float2*)&C[(size_t)(row0 + 8) * N + col] = make_float2(v2, v3);
        }
    }
}

// ---------------------------------------------------------------------------
// Batched transpose + RNA-round: WT[n][k] = rna(W[k][n]), 10 weights, one launch
// ---------------------------------------------------------------------------
#define NTSEG 10
struct TransJobs {
    const float* src[NTSEG];
    float*       dst[NTSEG];
    int          K[NTSEG];
    int          N[NTSEG];
};

__global__ __launch_bounds__(256)
void trans_all_kernel(TransJobs tj)
{
    const int seg = blockIdx.y;
    const int K = tj.K[seg], N = tj.N[seg];
    const int ntx = N >> 5;
    const int ntiles = (K >> 5) * ntx;
    if (blockIdx.x >= (unsigned)ntiles) return;
    const int nt = blockIdx.x % ntx;
    const int kt = blockIdx.x / ntx;

    __shared__ float smt[32][33];
    const float* W  = tj.src[seg];
    float* WT       = tj.dst[seg];

    const int c  = threadIdx.x & 31;
    const int r0 = threadIdx.x >> 5;   // 0..7
#pragma unroll
    for (int i = 0; i < 4; i++) {
        int r = r0 + i * 8;
        smt[r][c] = W[(size_t)(kt * 32 + r) * N + nt * 32 + c];
    }
    __syncthreads();
#pragma unroll
    for (int i = 0; i < 4; i++) {
        int r = r0 + i * 8;   // n-dim
        WT[(size_t)(nt * 32 + r) * K + kt * 32 + c] = tf32r(smt[c][r]);
    }
}

// ---------------------------------------------------------------------------
// Batched RNA-round (dec/enc): 2 segments in one launch
// ---------------------------------------------------------------------------
#define NSEG 2
struct RoundJobs {
    const float* src[NSEG];
    float*       dst[NSEG];
    int          n4[NSEG];
};

__global__ __launch_bounds__(256)
void round_all_kernel(RoundJobs rj)
{
    const int seg = blockIdx.y;
    const int i = blockIdx.x * 256 + threadIdx.x;
    if (i < rj.n4[seg]) {
        float4 v = ((const float4*)rj.src[seg])[i];
        ((float4*)rj.dst[seg])[i] =
            make_float4(tf32r(v.x), tf32r(v.y), tf32r(v.z), tf32r(v.w));
    }
}

// ---------------------------------------------------------------------------
// TF32 mma.sync flash attention, cp.async double-buffered K/V
// (exact round-7/12 shape). Block: 128 threads, 64 queries x one head.
// ---------------------------------------------------------------------------
#define AQ 64
#define AK 64
#define AST 68
#define KVW (AK * AST)
#define VBASE_W (2 * KVW)
#define PBASE_W (4 * KVW)
#define ATTN_SMEM ((4 * KVW + AQ * AST) * 4)

__global__ __launch_bounds__(128)
void attn_mma_kernel(const float* __restrict__ Q, const float* __restrict__ K,
                     const float* __restrict__ V, float* __restrict__ O,
                     int causal)
{
    extern __shared__ float sm[];
    const uint32_t sb = smem_u32(sm);
    const uint32_t* smu = (const uint32_t*)sm;
    float* Ps = sm + PBASE_W;

    const int tid  = threadIdx.x;
    const int warp = tid >> 5;
    const int lane = tid & 31;
    const int gid  = lane >> 2;
    const int tig  = lane & 3;

    const int qt = blockIdx.x;
    const int h  = blockIdx.y;
    const int b  = blockIdx.z;
    const int qbase = qt * AQ;
    const int mrow  = warp * 16;

    const int kr = tid >> 4;
    const int kc4 = tid & 15;
    const float* Kg = K + ((size_t)b * SS + kr) * DD + h * DHH + kc4 * 4;
    const float* Vg = V + ((size_t)b * SS + kr) * DD + h * DHH + kc4 * 4;
    const uint32_t koff = (uint32_t)((kr * AST + kc4 * 4) * 4);
    const uint32_t voff = (uint32_t)((VBASE_W + kr * AST + kc4 * 4) * 4);

    const int ntiles = causal ? (qt + 1) : (SS / AK);

    // issue tile 0
    {
#pragma unroll
        for (int i = 0; i < 8; i++) {
            cp16(sb + koff + (uint32_t)(i * 8 * AST * 4), Kg + (size_t)(i * 8) * DD);
            cp16(sb + voff + (uint32_t)(i * 8 * AST * 4), Vg + (size_t)(i * 8) * DD);
        }
        CP_COMMIT();
    }

    // stage Q (scaled + RNA rounded)
    const float qscale = 0.125f * 1.44269504f;
#pragma unroll
    for (int i = 0; i < 8; i++) {
        int f = tid + i * 128;
        int r = f >> 4, c4 = f & 15;
        float4 v4 = *(const float4*)&Q[((size_t)b * SS + qbase + r) * DD + h * DHH + c4 * 4];
        uint4 u = make_uint4(f2tf32(v4.x * qscale), f2tf32(v4.y * qscale),
                             f2tf32(v4.z * qscale), f2tf32(v4.w * qscale));
        *(uint4*)&Ps[r * AST + c4 * 4] = u;
    }
    __syncthreads();

    uint32_t qf[8][4];
#pragma unroll
    for (int ks = 0; ks < 8; ks++) {
        qf[ks][0] = smu[PBASE_W + (mrow + gid) * AST + ks * 8 + tig];
        qf[ks][1] = smu[PBASE_W + (mrow + gid + 8) * AST + ks * 8 + tig];
        qf[ks][2] = smu[PBASE_W + (mrow + gid) * AST + ks * 8 + tig + 4];
        qf[ks][3] = smu[PBASE_W + (mrow + gid + 8) * AST + ks * 8 + tig + 4];
    }

    float oacc[8][4];
#pragma unroll
    for (int nt = 0; nt < 8; nt++)
#pragma unroll
        for (int r = 0; r < 4; r++) oacc[nt][r] = 0.f;
    float m0 = -1e30f, m1 = -1e30f, l0 = 0.f, l1 = 0.f;

    for (int t = 0; t < ntiles; t++) {
        if (t + 1 < ntiles) {
            const int ns = (t + 1) & 1;
            const uint32_t kd = sb + koff + (uint32_t)(ns * KVW * 4);
            const uint32_t vd = sb + voff + (uint32_t)(ns * KVW * 4);
            const float* Kp = Kg + (size_t)(t + 1) * AK * DD;
            const float* Vp = Vg + (size_t)(t + 1) * AK * DD;
#pragma unroll
            for (int i = 0; i < 8; i++) {
                cp16(kd + (uint32_t)(i * 8 * AST * 4), Kp + (size_t)(i * 8) * DD);
                cp16(vd + (uint32_t)(i * 8 * AST * 4), Vp + (size_t)(i * 8) * DD);
            }
            CP_COMMIT();
            CP_WAIT(1);
        } else {
            CP_WAIT(0);
        }
        __syncthreads();

        const uint32_t kw = (t & 1) * KVW;
        const uint32_t vw = VBASE_W + (t & 1) * KVW;
        const int k0 = t * AK;

        float sacc[8][4];
#pragma unroll
        for (int nt = 0; nt < 8; nt++)
#pragma unroll
            for (int r = 0; r < 4; r++) sacc[nt][r] = 0.f;

#pragma unroll
        for (int ks = 0; ks < 8; ks++) {
            uint32_t bf[8][2];
            const int d0 = ks * 8 + tig;
#pragma unroll
            for (int nt = 0; nt < 8; nt++) {
                const uint32_t krow = kw + (nt * 8 + gid) * AST;
                bf[nt][0] = smu[krow + d0];
                bf[nt][1] = smu[krow + d0 + 4];
            }
#pragma unroll
            for (int nt = 0; nt < 8; nt++)
                mma_tf32(sacc[nt], qf[ks], bf[nt]);
        }

        if (causal && t == qt) {
            int q0 = qbase + mrow + gid;
            int q1 = q0 + 8;
#pragma unroll
            for (int nt = 0; nt < 8; nt++) {
                int key = k0 + nt * 8 + tig * 2;
                if (key > q0)     sacc[nt][0] = -1e30f;
                if (key + 1 > q0) sacc[nt][1] = -1e30f;
                if (key > q1)     sacc[nt][2] = -1e30f;
                if (key + 1 > q1) sacc[nt][3] = -1e30f;
            }
        }

        float mx0 = -1e30f, mx1 = -1e30f;
#pragma unroll
        for (int nt = 0; nt < 8; nt++) {
            mx0 = fmaxf(mx0, fmaxf(sacc[nt][0], sacc[nt][1]));
            mx1 = fmaxf(mx1, fmaxf(sacc[nt][2], sacc[nt][3]));
        }
        mx0 = fmaxf(mx0, __shfl_xor_sync(0xffffffffu, mx0, 1));
        mx0 = fmaxf(mx0, __shfl_xor_sync(0xffffffffu, mx0, 2));
        mx1 = fmaxf(mx1, __shfl_xor_sync(0xffffffffu, mx1, 1));
        mx1 = fmaxf(mx1, __shfl_xor_sync(0xffffffffu, mx1, 2));

        float nm0 = fmaxf(m0, mx0), nm1 = fmaxf(m1, mx1);
        float c0 = exp2f(m0 - nm0), c1 = exp2f(m1 - nm1);
        m0 = nm0; m1 = nm1;

        float rs0 = 0.f, rs1 = 0.f;
#pragma unroll
        for (int nt = 0; nt < 8; nt++) {
            float p0 = exp2f(sacc[nt][0] - m0);
            float p1 = exp2f(sacc[nt][1] - m0);
            float p2 = exp2f(sacc[nt][2] - m1);
            float p3 = exp2f(sacc[nt][3] - m1);
            rs0 += p0 + p1;
            rs1 += p2 + p3;
            oacc[nt][0] *= c0; oacc[nt][1] *= c0;
            oacc[nt][2] *= c1; oacc[nt][3] *= c1;
            uint2 u01 = make_uint2(f2tf32(p0), f2tf32(p1));
            uint2 u23 = make_uint2(f2tf32(p2), f2tf32(p3));
            *(uint2*)&Ps[(mrow + gid) * AST + nt * 8 + tig * 2]     = u01;
            *(uint2*)&Ps[(mrow + gid + 8) * AST + nt * 8 + tig * 2] = u23;
        }
        rs0 += __shfl_xor_sync(0xffffffffu, rs0, 1);
        rs0 += __shfl_xor_sync(0xffffffffu, rs0, 2);
        rs1 += __shfl_xor_sync(0xffffffffu, rs1, 1);
        rs1 += __shfl_xor_sync(0xffffffffu, rs1, 2);
        l0 = l0 * c0 + rs0;
        l1 = l1 * c1 + rs1;
        __syncwarp();

#pragma unroll
        for (int ks = 0; ks < 8; ks++) {
            uint32_t af[4];
            af[0] = smu[PBASE_W + (mrow + gid) * AST + ks * 8 + tig];
            af[1] = smu[PBASE_W + (mrow + gid + 8) * AST + ks * 8 + tig];
            af[2] = smu[PBASE_W + (mrow + gid) * AST + ks * 8 + tig + 4];
            af[3] = smu[PBASE_W + (mrow + gid + 8) * AST + ks * 8 + tig + 4];
            uint32_t bf[8][2];
            const uint32_t vr0 = vw + (ks * 8 + tig) * AST;
            const uint32_t vr1 = vw + (ks * 8 + tig + 4) * AST;
#pragma unroll
            for (int nt = 0; nt < 8; nt++) {
                bf[nt][0] = smu[vr0 + nt * 8 + gid];
                bf[nt][1] = smu[vr1 + nt * 8 + gid];
            }
#pragma unroll
            for (int nt = 0; nt < 8; nt++)
                mma_tf32(oacc[nt], af, bf[nt]);
        }
        __syncthreads();
    }

    float inv0 = 1.f / l0, inv1 = 1.f / l1;
    int row0 = qbase + mrow + gid;
#pragma unroll
    for (int nt = 0; nt < 8; nt++) {
        int col = h * DHH + nt * 8 + tig * 2;
        *(float2*)&O[((size_t)b * SS + row0) * DD + col] =
            make_float2(tf32r(oacc[nt][0] * inv0), tf32r(oacc[nt][1] * inv0));
        *(float2*)&O[((size_t)b * SS + row0 + 8) * DD + col] =
            make_float2(tf32r(oacc[nt][2] * inv1), tf32r(oacc[nt][3] * inv1));
    }
}

// ---------------------------------------------------------------------------
// out = LayerNorm(a + res) * g + bt ; optional second rounded output
// ---------------------------------------------------------------------------
__inline__ __device__ float warp_sum(float v)
{
#pragma unroll
    for (int o = 16; o > 0; o >>= 1) v += __shfl_xor_sync(0xffffffffu, v, o);
    return v;
}

__global__ __launch_bounds__(256)
void add_ln_kernel(const float* __restrict__ a, const float* __restrict__ res,
                   const float* __restrict__ g, const float* __restrict__ bt,
                   float* __restrict__ out, float* __restrict__ out_r)
{
    __shared__ float buf[DD];
    __shared__ float red1[8], red2[8];

    const size_t row = blockIdx.x;
    const float* ap = a + row * DD;
    const float* rp = res + row * DD;

    float sum = 0.f, sq = 0.f;
    for (int i = threadIdx.x; i < DD; i += 256) {
        float v = ap[i] + rp[i];
        buf[i] = v;
        sum += v;
        sq  = fmaf(v, v, sq);
    }
    sum = warp_sum(sum);
    sq  = warp_sum(sq);
    int warp = threadIdx.x >> 5, lane = threadIdx.x & 31;
    if (lane == 0) { red1[warp] = sum; red2[warp] = sq; }
    __syncthreads();
    if (warp == 0) {
        float s1 = lane < 8 ? red1[lane] : 0.f;
        float s2 = lane < 8 ? red2[lane] : 0.f;
        s1 = warp_sum(s1);
        s2 = warp_sum(s2);
        if (lane == 0) { red1[0] = s1; red2[0] = s2; }
    }
    __syncthreads();
    float mu  = red1[0] * (1.f / DD);
    float var = red2[0] * (1.f / DD) - mu * mu;
    float rstd = rsqrtf(var + 1e-5f);

    for (int i = threadIdx.x; i < DD; i += 256) {
        float v = (buf[i] - mu) * rstd * g[i] + bt[i];
        out[row * DD + i] = v;
        if (out_r) out_r[row * DD + i] = tf32r(v);
    }
}

// ---------------------------------------------------------------------------
// Host orchestration
// ---------------------------------------------------------------------------
static void launch_gemm(const float* A, const float* WT, const float* bias,
                        float* C, int M, int N, int K, int relu, int rnd)
{
    dim3 grid(N / 128, M / 128);
    gemm_cp_kernel<<<grid, 256, GEMM_SMEM>>>(A, WT, bias, C, M, N, K, relu, rnd);
}

extern "C" void kernel_launch(void* const* d_in, const int* in_sizes, int n_in,
                              void* d_out, int out_size)
{
    (void)in_sizes; (void)n_in; (void)out_size;

    const float* enc = (const float*)d_in[0];
    const float* dec = (const float*)d_in[1];
    const float* sa_wq = (const float*)d_in[2];
    const float* sa_bq = (const float*)d_in[3];
    const float* sa_wk = (const float*)d_in[4];
    const float* sa_bk = (const float*)d_in[5];
    const float* sa_wv = (const float*)d_in[6];
    const float* sa_bv = (const float*)d_in[7];
    const float* sa_wo = (const float*)d_in[8];
    const float* sa_bo = (const float*)d_in[9];
    const float* sa_g  = (const float*)d_in[10];
    const float* sa_bt = (const float*)d_in[11];
    const float* ca_wq = (const float*)d_in[12];
    const float* ca_bq = (const float*)d_in[13];
    const float* ca_wk = (const float*)d_in[14];
    const float* ca_bk = (const float*)d_in[15];
    const float* ca_wv = (const float*)d_in[16];
    const float* ca_bv = (const float*)d_in[17];
    const float* ca_wo = (const float*)d_in[18];
    const float* ca_bo = (const float*)d_in[19];
    const float* ca_g  = (const float*)d_in[20];
    const float* ca_bt = (const float*)d_in[21];
    const float* f_w1 = (const float*)d_in[22];
    const float* f_b1 = (const float*)d_in[23];
    const float* f_w2 = (const float*)d_in[24];
    const float* f_b2 = (const float*)d_in[25];
    const float* f_g  = (const float*)d_in[26];
    const float* f_bt = (const float*)d_in[27];

    float* out = (float*)d_out;

    void *pq, *pk, *pv, *pa, *pt, *px, *py, *ph, *pwt, *pdr, *per, *pxr, *pyr;
    cudaGetSymbolAddress(&pq, g_q);
    cudaGetSymbolAddress(&pk, g_k);
    cudaGetSymbolAddress(&pv, g_v);
    cudaGetSymbolAddress(&pa, g_a);
    cudaGetSymbolAddress(&pt, g_t);
    cudaGetSymbolAddress(&px, g_x);
    cudaGetSymbolAddress(&py, g_y);
    cudaGetSymbolAddress(&ph, g_h);
    cudaGetSymbolAddress(&pwt, g_wt);
    cudaGetSymbolAddress(&pdr, g_dr);
    cudaGetSymbolAddress(&per, g_er);
    cudaGetSymbolAddress(&pxr, g_xr);
    cudaGetSymbolAddress(&pyr, g_yr);
    float* q = (float*)pq; float* k = (float*)pk; float* v = (float*)pv;
    float* a = (float*)pa; float* t = (float*)pt; float* x = (float*)px;
    float* y = (float*)py; float* h = (float*)ph;
    float* wt = (float*)pwt;
    float* dr = (float*)pdr; float* er = (float*)per;
    float* xr = (float*)pxr; float* yr = (float*)pyr;

    cudaFuncSetAttribute(attn_mma_kernel,
                         cudaFuncAttributeMaxDynamicSharedMemorySize, ATTN_SMEM);
    cudaFuncSetAttribute(gemm_cp_kernel,
                         cudaFuncAttributeMaxDynamicSharedMemorySize, GEMM_SMEM);

    // transposed+rounded weight slices in g_wt (units of 1M floats)
    const size_t U = (size_t)1024 * 1024;
    float* w_sa_q = wt + 0 * U;
    float* w_sa_k = wt + 1 * U;
    float* w_sa_v = wt + 2 * U;
    float* w_sa_o = wt + 3 * U;
    float* w_ca_q = wt + 4 * U;
    float* w_ca_k = wt + 5 * U;
    float* w_ca_v = wt + 6 * U;
    float* w_ca_o = wt + 7 * U;
    float* w_f1   = wt + 8 * U;    // [FF][DD] = 4M floats
    float* w_f2   = wt + 12 * U;   // [DD][FF] = 4M floats

    // fused transpose+round for 10 weights
    {
        TransJobs tj;
        const float* srcs[NTSEG] = { sa_wq, sa_wk, sa_wv, sa_wo,
                                     ca_wq, ca_wk, ca_wv, ca_wo,
                                     f_w1, f_w2 };
        float* dsts[NTSEG] = { w_sa_q, w_sa_k, w_sa_v, w_sa_o,
                               w_ca_q, w_ca_k, w_ca_v, w_ca_o,
                               w_f1, w_f2 };
        int Ks[NTSEG] = { DD, DD, DD, DD, DD, DD, DD, DD, DD, FF };
        int Ns[NTSEG] = { DD, DD, DD, DD, DD, DD, DD, DD, FF, DD };
        for (int i = 0; i < NTSEG; i++) {
            tj.src[i] = srcs[i]; tj.dst[i] = dsts[i];
            tj.K[i] = Ks[i]; tj.N[i] = Ns[i];
        }
        dim3 tg(4096, NTSEG);
        trans_all_kernel<<<tg, 256>>>(tj);
    }
    // fused round for dec/enc
    {
        RoundJobs rj;
        rj.src[0] = dec; rj.dst[0] = dr; rj.n4[0] = MM * DD / 4;
        rj.src[1] = enc; rj.dst[1] = er; rj.n4[1] = MM * DD / 4;
        dim3 rg(4096, NSEG);
        round_all_kernel<<<rg, 256>>>(rj);
    }

    dim3 agrid(SS / AQ, HH, BB);

    // ---- self attention (causal) ----
    launch_gemm(dr, w_sa_q, sa_bq, q, MM, DD, DD, 0, 1);
    launch_gemm(dr, w_sa_k, sa_bk, k, MM, DD, DD, 0, 1);
    launch_gemm(dr, w_sa_v, sa_bv, v, MM, DD, DD, 0, 1);
    attn_mma_kernel<<<agrid, 128, ATTN_SMEM>>>(q, k, v, a, 1);
    launch_gemm(a, w_sa_o, sa_bo, t, MM, DD, DD, 0, 0);
    add_ln_kernel<<<MM, 256>>>(t, dec, sa_g, sa_bt, x, xr);

    // ---- cross attention (non-causal) ----
    launch_gemm(xr, w_ca_q, ca_bq, q, MM, DD, DD, 0, 1);
    launch_gemm(er, w_ca_k, ca_bk, k, MM, DD, DD, 0, 1);
    launch_gemm(er, w_ca_v, ca_bv, v, MM, DD, DD, 0, 1);
    attn_mma_kernel<<<agrid, 128, ATTN_SMEM>>>(q, k, v, a, 0);
    launch_gemm(a, w_ca_o, ca_bo, t, MM, DD, DD, 0, 0);
    add_ln_kernel<<<MM, 256>>>(t, x, ca_g, ca_bt, y, yr);

    // ---- FFN ----
    launch_gemm(yr, w_f1, f_b1, h, MM, FF, DD, 1, 1);
    launch_gemm(h, w_f2, f_b2, t, MM, DD, FF, 0, 0);
    add_ln_kernel<<<MM, 256>>>(t, y, f_g, f_bt, out, (float*)nullptr);
}

// round 15
// speedup vs baseline: 1.0279x; 1.0279x over previous
#include <cuda_runtime.h>
#include <cuda_bf16.h>
#include <math.h>
#include <stdint.h>

// Problem constants
#define BB 2
#define SS 2048
#define DD 1024
#define HH 16
#define DHH 64
#define FF 4096
#define MM (BB * SS)   // 4096 rows total

// ---------------------------------------------------------------------------
// Scratch buffers (__device__ globals; no allocation allowed)
// ---------------------------------------------------------------------------
__device__ float g_q[(size_t)MM * DD];
__device__ float g_k[(size_t)MM * DD];
__device__ float g_v[(size_t)MM * DD];
__device__ float g_a[(size_t)MM * DD];
__device__ float g_t[(size_t)MM * DD];
__device__ float g_x[(size_t)MM * DD];
__device__ float g_y[(size_t)MM * DD];
__device__ float g_h[(size_t)MM * FF];
__device__ float g_wt[(size_t)16 * 1024 * 1024];  // all rounded weights (64MB)
__device__ float g_dr[(size_t)MM * DD];   // rounded decoder input
__device__ float g_er[(size_t)MM * DD];   // rounded encoder output
__device__ float g_xr[(size_t)MM * DD];   // rounded x
__device__ float g_yr[(size_t)MM * DD];   // rounded y

// ---------------------------------------------------------------------------
// Helpers
// ---------------------------------------------------------------------------
__device__ __forceinline__ uint32_t f2tf32(float x)
{
    uint32_t r;
    asm("cvt.rna.tf32.f32 %0, %1;" : "=r"(r) : "f"(x));
    return r;
}

__device__ __forceinline__ float tf32r(float x)
{
    return __uint_as_float(f2tf32(x));
}

__device__ __forceinline__ uint32_t smem_u32(const void* p)
{
    uint32_t a;
    asm("{ .reg .u64 t; cvta.to.shared.u64 t, %1; cvt.u32.u64 %0, t; }"
        : "=r"(a) : "l"(p));
    return a;
}

__device__ __forceinline__ void cp16(uint32_t dst, const void* src)
{
    asm volatile("cp.async.cg.shared.global [%0], [%1], 16;"
                 :: "r"(dst), "l"(src));
}

#define CP_COMMIT()  asm volatile("cp.async.commit_group;" ::: "memory")
#define CP_WAIT(n)   asm volatile("cp.async.wait_group %0;" :: "n"(n) : "memory")

__device__ __forceinline__ void mma_tf32(float* c, const uint32_t* a, const uint32_t* b)
{
    asm volatile(
        "mma.sync.aligned.m16n8k8.row.col.f32.tf32.tf32.f32 "
        "{%0,%1,%2,%3}, {%4,%5,%6,%7}, {%8,%9}, {%0,%1,%2,%3};"
        : "+f"(c[0]), "+f"(c[1]), "+f"(c[2]), "+f"(c[3])
        : "r"(a[0]), "r"(a[1]), "r"(a[2]), "r"(a[3]), "r"(b[0]), "r"(b[1]));
}

// ---------------------------------------------------------------------------
// TF32 GEMM, cp.async 4-stage pipeline (round-12 body), batched over z.
// C[z] = A[z][M,K] @ W[z][K,N] + bias[z][N]; operands pre-rounded tf32.
// 128x128 CTA tile, BK=16, 256 threads (8 warps 2x4), warp tile 64x32.
// As: [4][128][20] floats, Bs: [4][16][136] floats.
// ---------------------------------------------------------------------------
#define ASTR 20
#define BSTR 136
#define AWORDS (128 * ASTR)
#define BWORDS (16 * BSTR)
#define BBASE_W (4 * AWORDS)
#define GEMM_SMEM ((4 * AWORDS + 4 * BWORDS) * 4)

struct GemmBatch {
    const float* A[3];
    const float* W[3];
    const float* bias[3];
    float*       C[3];
};

__global__ __launch_bounds__(256)
void gemm_cp_kernel(GemmBatch gb, int M, int N, int K, int relu, int rnd)
{
    extern __shared__ float sm[];
    const uint32_t sb = smem_u32(sm);
    const uint32_t* smu = (const uint32_t*)sm;

    const float* __restrict__ A    = gb.A[blockIdx.z];
    const float* __restrict__ W    = gb.W[blockIdx.z];
    const float* __restrict__ bias = gb.bias[blockIdx.z];
    float* __restrict__ C          = gb.C[blockIdx.z];

    const int tid  = threadIdx.x;
    const int warp = tid >> 5;
    const int lane = tid & 31;
    const int wm   = warp >> 2;       // 0..1
    const int wn   = warp & 3;        // 0..3
    const int gid  = lane >> 2;       // 0..7
    const int tig  = lane & 3;        // 0..3

    const int bm = blockIdx.y * 128;
    const int bn = blockIdx.x * 128;

    const int a_row = tid >> 2;       // 0..63 (+64)
    const int a_c4  = tid & 3;
    const int b_row = tid >> 5;       // 0..7 (+8)
    const int b_c4  = tid & 31;

    const float* Ag = A + (size_t)(bm + a_row) * K + a_c4 * 4;
    const float* Wg = W + (size_t)b_row * N + bn + b_c4 * 4;

    const uint32_t aoff0 = (uint32_t)((a_row * ASTR + a_c4 * 4) * 4);
    const uint32_t aoff1 = (uint32_t)(((a_row + 64) * ASTR + a_c4 * 4) * 4);
    const uint32_t boff0 = (uint32_t)((BBASE_W + b_row * BSTR + b_c4 * 4) * 4);
    const uint32_t boff1 = (uint32_t)((BBASE_W + (b_row + 8) * BSTR + b_c4 * 4) * 4);

    float acc[4][4][4];
#pragma unroll
    for (int i = 0; i < 4; i++)
#pragma unroll
        for (int j = 0; j < 4; j++)
#pragma unroll
            for (int r = 0; r < 4; r++) acc[i][j][r] = 0.f;

    const int T = K >> 4;

    // prologue: stages 0..2
#pragma unroll
    for (int s = 0; s < 3; s++) {
        const int k0 = s * 16;
        const uint32_t sa = sb + (uint32_t)(s * AWORDS * 4);
        const uint32_t sbb = sb + (uint32_t)(s * BWORDS * 4);
        cp16(sa + aoff0, Ag + k0);
        cp16(sa + aoff1, Ag + (size_t)64 * K + k0);
        cp16(sbb + boff0, Wg + (size_t)k0 * N);
        cp16(sbb + boff1, Wg + (size_t)(k0 + 8) * N);
        CP_COMMIT();
    }

    for (int it = 0; it < T; it++) {
        CP_WAIT(2);
        __syncthreads();

        const int st = it & 3;
        const uint32_t aw = st * AWORDS;
        const uint32_t bw = BBASE_W + st * BWORDS;

#pragma unroll
        for (int kk = 0; kk < 2; kk++) {
            uint32_t af[4][4], bf[4][2];
            const int kb = kk * 8;
#pragma unroll
            for (int mt = 0; mt < 4; mt++) {
                int mrow = wm * 64 + mt * 16;
                af[mt][0] = smu[aw + (mrow + gid) * ASTR + kb + tig];
                af[mt][1] = smu[aw + (mrow + gid + 8) * ASTR + kb + tig];
                af[mt][2] = smu[aw + (mrow + gid) * ASTR + kb + tig + 4];
                af[mt][3] = smu[aw + (mrow + gid + 8) * ASTR + kb + tig + 4];
            }
#pragma unroll
            for (int nt = 0; nt < 4; nt++) {
                int ncol = wn * 32 + nt * 8;
                bf[nt][0] = smu[bw + (kb + tig) * BSTR + ncol + gid];
                bf[nt][1] = smu[bw + (kb + tig + 4) * BSTR + ncol + gid];
            }
#pragma unroll
            for (int mt = 0; mt < 4; mt++)
#pragma unroll
                for (int nt = 0; nt < 4; nt++)
                    mma_tf32(acc[mt][nt], af[mt], bf[nt]);
        }

        if (it + 3 < T) {
            const int ns = (it + 3) & 3;
            const int k0 = (it + 3) * 16;
            const uint32_t sa = sb + (uint32_t)(ns * AWORDS * 4);
            const uint32_t sbb = sb + (uint32_t)(ns * BWORDS * 4);
            cp16(sa + aoff0, Ag + k0);
            cp16(sa + aoff1, Ag + (size_t)64 * K + k0);
            cp16(sbb + boff0, Wg + (size_t)k0 * N);
            cp16(sbb + boff1, Wg + (size_t)(k0 + 8) * N);
        }
        CP_COMMIT();
    }

    // epilogue
#pragma unroll
    for (int mt = 0; mt < 4; mt++) {
        int row0 = bm + wm * 64 + mt * 16 + gid;
#pragma unroll
        for (int nt = 0; nt < 4; nt++) {
            int col = bn + wn * 32 + nt * 8 + tig * 2;
            float b0 = bias[col], b1 = bias[col + 1];
            float v0 = acc[mt][nt][0] + b0;
            float v1 = acc[mt][nt][1] + b1;
            float v2 = acc[mt][nt][2] + b0;
            float v3 = acc[mt][nt][3] + b1;
            if (relu) {
                v0 = fmaxf(v0, 0.f); v1 = fmaxf(v1, 0.f);
                v2 = fmaxf(v2, 0.f); v3 = fmaxf(v3, 0.f);
            }
            if (rnd) {
                v0 = tf32r(v0); v1 = tf32r(v1);
                v2 = tf32r(v2); v3 = tf32r(v3);
            }
            *(float2*)&C[(size_t)row0 * N + col]       = make_float2(v0, v1);
            *(float2*)&C[(size_t)(row0 + 8) * N + col] = make_float2(v2, v3);
        }
    }
}

// ---------------------------------------------------------------------------
// Batched RNA-round: 12 segments in one launch (grid.y = segment)
// ---------------------------------------------------------------------------
#define NSEG 12
struct RoundJobs {
    const float* src[NSEG];
    float*       dst[NSEG];
    int          n4[NSEG];
};

__global__ __launch_bounds__(256)
void round_all_kernel(RoundJobs rj)
{
    const int seg = blockIdx.y;
    const int i = blockIdx.x * 256 + threadIdx.x;
    if (i < rj.n4[seg]) {
        float4 v = ((const float4*)rj.src[seg])[i];
        ((float4*)rj.dst[seg])[i] =
            make_float4(tf32r(v.x), tf32r(v.y), tf32r(v.z), tf32r(v.w));
    }
}

// ---------------------------------------------------------------------------
// TF32 mma.sync flash attention, cp.async double-buffered K/V
// (exact round-7/12 shape). Block: 128 threads, 64 queries x one head.
// ---------------------------------------------------------------------------
#define AQ 64
#define AK 64
#define AST 68
#define KVW (AK * AST)
#define VBASE_W (2 * KVW)
#define PBASE_W (4 * KVW)
#define ATTN_SMEM ((4 * KVW + AQ * AST) * 4)

__global__ __launch_bounds__(128)
void attn_mma_kernel(const float* __restrict__ Q, const float* __restrict__ K,
                     const float* __restrict__ V, float* __restrict__ O,
                     int causal)
{
    extern __shared__ float sm[];
    const uint32_t sb = smem_u32(sm);
    const uint32_t* smu = (const uint32_t*)sm;
    float* Ps = sm + PBASE_W;

    const int tid  = threadIdx.x;
    const int warp = tid >> 5;
    const int lane = tid & 31;
    const int gid  = lane >> 2;
    const int tig  = lane & 3;

    const int qt = blockIdx.x;
    const int h  = blockIdx.y;
    const int b  = blockIdx.z;
    const int qbase = qt * AQ;
    const int mrow  = warp * 16;

    const int kr = tid >> 4;
    const int kc4 = tid & 15;
    const float* Kg = K + ((size_t)b * SS + kr) * DD + h * DHH + kc4 * 4;
    const float* Vg = V + ((size_t)b * SS + kr) * DD + h * DHH + kc4 * 4;
    const uint32_t koff = (uint32_t)((kr * AST + kc4 * 4) * 4);
    const uint32_t voff = (uint32_t)((VBASE_W + kr * AST + kc4 * 4) * 4);

    const int ntiles = causal ? (qt + 1) : (SS / AK);

    // issue tile 0
    {
#pragma unroll
        for (int i = 0; i < 8; i++) {
            cp16(sb + koff + (uint32_t)(i * 8 * AST * 4), Kg + (size_t)(i * 8) * DD);
            cp16(sb + voff + (uint32_t)(i * 8 * AST * 4), Vg + (size_t)(i * 8) * DD);
        }
        CP_COMMIT();
    }

    // stage Q (scaled + RNA rounded)
    const float qscale = 0.125f * 1.44269504f;
#pragma unroll
    for (int i = 0; i < 8; i++) {
        int f = tid + i * 128;
        int r = f >> 4, c4 = f & 15;
        float4 v4 = *(const float4*)&Q[((size_t)b * SS + qbase + r) * DD + h * DHH + c4 * 4];
        uint4 u = make_uint4(f2tf32(v4.x * qscale), f2tf32(v4.y * qscale),
                             f2tf32(v4.z * qscale), f2tf32(v4.w * qscale));
        *(uint4*)&Ps[r * AST + c4 * 4] = u;
    }
    __syncthreads();

    uint32_t qf[8][4];
#pragma unroll
    for (int ks = 0; ks < 8; ks++) {
        qf[ks][0] = smu[PBASE_W + (mrow + gid) * AST + ks * 8 + tig];
        qf[ks][1] = smu[PBASE_W + (mrow + gid + 8) * AST + ks * 8 + tig];
        qf[ks][2] = smu[PBASE_W + (mrow + gid) * AST + ks * 8 + tig + 4];
        qf[ks][3] = smu[PBASE_W + (mrow + gid + 8) * AST + ks * 8 + tig + 4];
    }

    float oacc[8][4];
#pragma unroll
    for (int nt = 0; nt < 8; nt++)
#pragma unroll
        for (int r = 0; r < 4; r++) oacc[nt][r] = 0.f;
    float m0 = -1e30f, m1 = -1e30f, l0 = 0.f, l1 = 0.f;

    for (int t = 0; t < ntiles; t++) {
        if (t + 1 < ntiles) {
            const int ns = (t + 1) & 1;
            const uint32_t kd = sb + koff + (uint32_t)(ns * KVW * 4);
            const uint32_t vd = sb + voff + (uint32_t)(ns * KVW * 4);
            const float* Kp = Kg + (size_t)(t + 1) * AK * DD;
            const float* Vp = Vg + (size_t)(t + 1) * AK * DD;
#pragma unroll
            for (int i = 0; i < 8; i++) {
                cp16(kd + (uint32_t)(i * 8 * AST * 4), Kp + (size_t)(i * 8) * DD);
                cp16(vd + (uint32_t)(i * 8 * AST * 4), Vp + (size_t)(i * 8) * DD);
            }
            CP_COMMIT();
            CP_WAIT(1);
        } else {
            CP_WAIT(0);
        }
        __syncthreads();

        const uint32_t kw = (t & 1) * KVW;
        const uint32_t vw = VBASE_W + (t & 1) * KVW;
        const int k0 = t * AK;

        float sacc[8][4];
#pragma unroll
        for (int nt = 0; nt < 8; nt++)
#pragma unroll
            for (int r = 0; r < 4; r++) sacc[nt][r] = 0.f;

#pragma unroll
        for (int ks = 0; ks < 8; ks++) {
            uint32_t bf[8][2];
            const int d0 = ks * 8 + tig;
#pragma unroll
            for (int nt = 0; nt < 8; nt++) {
                const uint32_t krow = kw + (nt * 8 + gid) * AST;
                bf[nt][0] = smu[krow + d0];
                bf[nt][1] = smu[krow + d0 + 4];
            }
#pragma unroll
            for (int nt = 0; nt < 8; nt++)
                mma_tf32(sacc[nt], qf[ks], bf[nt]);
        }

        if (causal && t == qt) {
            int q0 = qbase + mrow + gid;
            int q1 = q0 + 8;
#pragma unroll
            for (int nt = 0; nt < 8; nt++) {
                int key = k0 + nt * 8 + tig * 2;
                if (key > q0)     sacc[nt][0] = -1e30f;
                if (key + 1 > q0) sacc[nt][1] = -1e30f;
                if (key > q1)     sacc[nt][2] = -1e30f;
                if (key + 1 > q1) sacc[nt][3] = -1e30f;
            }
        }

        float mx0 = -1e30f, mx1 = -1e30f;
#pragma unroll
        for (int nt = 0; nt < 8; nt++) {
            mx0 = fmaxf(mx0, fmaxf(sacc[nt][0], sacc[nt][1]));
            mx1 = fmaxf(mx1, fmaxf(sacc[nt][2], sacc[nt][3]));
        }
        mx0 = fmaxf(mx0, __shfl_xor_sync(0xffffffffu, mx0, 1));
        mx0 = fmaxf(mx0, __shfl_xor_sync(0xffffffffu, mx0, 2));
        mx1 = fmaxf(mx1, __shfl_xor_sync(0xffffffffu, mx1, 1));
        mx1 = fmaxf(mx1, __shfl_xor_sync(0xffffffffu, mx1, 2));

        float nm0 = fmaxf(m0, mx0), nm1 = fmaxf(m1, mx1);
        float c0 = exp2f(m0 - nm0), c1 = exp2f(m1 - nm1);
        m0 = nm0; m1 = nm1;

        float rs0 = 0.f, rs1 = 0.f;
#pragma unroll
        for (int nt = 0; nt < 8; nt++) {
            float p0 = exp2f(sacc[nt][0] - m0);
            float p1 = exp2f(sacc[nt][1] - m0);
            float p2 = exp2f(sacc[nt][2] - m1);
            float p3 = exp2f(sacc[nt][3] - m1);
            rs0 += p0 + p1;
            rs1 += p2 + p3;
            oacc[nt][0] *= c0; oacc[nt][1] *= c0;
            oacc[nt][2] *= c1; oacc[nt][3] *= c1;
            uint2 u01 = make_uint2(f2tf32(p0), f2tf32(p1));
            uint2 u23 = make_uint2(f2tf32(p2), f2tf32(p3));
            *(uint2*)&Ps[(mrow + gid) * AST + nt * 8 + tig * 2]     = u01;
            *(uint2*)&Ps[(mrow + gid + 8) * AST + nt * 8 + tig * 2] = u23;
        }
        rs0 += __shfl_xor_sync(0xffffffffu, rs0, 1);
        rs0 += __shfl_xor_sync(0xffffffffu, rs0, 2);
        rs1 += __shfl_xor_sync(0xffffffffu, rs1, 1);
        rs1 += __shfl_xor_sync(0xffffffffu, rs1, 2);
        l0 = l0 * c0 + rs0;
        l1 = l1 * c1 + rs1;
        __syncwarp();

#pragma unroll
        for (int ks = 0; ks < 8; ks++) {
            uint32_t af[4];
            af[0] = smu[PBASE_W + (mrow + gid) * AST + ks * 8 + tig];
            af[1] = smu[PBASE_W + (mrow + gid + 8) * AST + ks * 8 + tig];
            af[2] = smu[PBASE_W + (mrow + gid) * AST + ks * 8 + tig + 4];
            af[3] = smu[PBASE_W + (mrow + gid + 8) * AST + ks * 8 + tig + 4];
            uint32_t bf[8][2];
            const uint32_t vr0 = vw + (ks * 8 + tig) * AST;
            const uint32_t vr1 = vw + (ks * 8 + tig + 4) * AST;
#pragma unroll
            for (int nt = 0; nt < 8; nt++) {
                bf[nt][0] = smu[vr0 + nt * 8 + gid];
                bf[nt][1] = smu[vr1 + nt * 8 + gid];
            }
#pragma unroll
            for (int nt = 0; nt < 8; nt++)
                mma_tf32(oacc[nt], af, bf[nt]);
        }
        __syncthreads();
    }

    float inv0 = 1.f / l0, inv1 = 1.f / l1;
    int row0 = qbase + mrow + gid;
#pragma unroll
    for (int nt = 0; nt < 8; nt++) {
        int col = h * DHH + nt * 8 + tig * 2;
        *(float2*)&O[((size_t)b * SS + row0) * DD + col] =
            make_float2(tf32r(oacc[nt][0] * inv0), tf32r(oacc[nt][1] * inv0));
        *(float2*)&O[((size_t)b * SS + row0 + 8) * DD + col] =
            make_float2(tf32r(oacc[nt][2] * inv1), tf32r(oacc[nt][3] * inv1));
    }
}

// ---------------------------------------------------------------------------
// out = LayerNorm(a + res) * g + bt ; optional second rounded output
// ---------------------------------------------------------------------------
__inline__ __device__ float warp_sum(float v)
{
#pragma unroll
    for (int o = 16; o > 0; o >>= 1) v += __shfl_xor_sync(0xffffffffu, v, o);
    return v;
}

__global__ __launch_bounds__(256)
void add_ln_kernel(const float* __restrict__ a, const float* __restrict__ res,
                   const float* __restrict__ g, const float* __restrict__ bt,
                   float* __restrict__ out, float* __restrict__ out_r)
{
    __shared__ float buf[DD];
    __shared__ float red1[8], red2[8];

    const size_t row = blockIdx.x;
    const float* ap = a + row * DD;
    const float* rp = res + row * DD;

    float sum = 0.f, sq = 0.f;
    for (int i = threadIdx.x; i < DD; i += 256) {
        float v = ap[i] + rp[i];
        buf[i] = v;
        sum += v;
        sq  = fmaf(v, v, sq);
    }
    sum = warp_sum(sum);
    sq  = warp_sum(sq);
    int warp = threadIdx.x >> 5, lane = threadIdx.x & 31;
    if (lane == 0) { red1[warp] = sum; red2[warp] = sq; }
    __syncthreads();
    if (warp == 0) {
        float s1 = lane < 8 ? red1[lane] : 0.f;
        float s2 = lane < 8 ? red2[lane] : 0.f;
        s1 = warp_sum(s1);
        s2 = warp_sum(s2);
        if (lane == 0) { red1[0] = s1; red2[0] = s2; }
    }
    __syncthreads();
    float mu  = red1[0] * (1.f / DD);
    float var = red2[0] * (1.f / DD) - mu * mu;
    float rstd = rsqrtf(var + 1e-5f);

    for (int i = threadIdx.x; i < DD; i += 256) {
        float v = (buf[i] - mu) * rstd * g[i] + bt[i];
        out[row * DD + i] = v;
        if (out_r) out_r[row * DD + i] = tf32r(v);
    }
}

// ---------------------------------------------------------------------------
// Host orchestration
// ---------------------------------------------------------------------------
static void launch_gemm1(const float* A, const float* W, const float* bias,
                         float* C, int M, int N, int K, int relu, int rnd)
{
    GemmBatch gb;
    gb.A[0] = gb.A[1] = gb.A[2] = A;
    gb.W[0] = gb.W[1] = gb.W[2] = W;
    gb.bias[0] = gb.bias[1] = gb.bias[2] = bias;
    gb.C[0] = gb.C[1] = gb.C[2] = C;
    dim3 grid(N / 128, M / 128, 1);
    gemm_cp_kernel<<<grid, 256, GEMM_SMEM>>>(gb, M, N, K, relu, rnd);
}

static void launch_gemm_qkv(const float* Aq, const float* Akv,
                            const float* Wq, const float* Wk, const float* Wv,
                            const float* bq, const float* bk, const float* bv,
                            float* Cq, float* Ck, float* Cv)
{
    GemmBatch gb;
    gb.A[0] = Aq;  gb.A[1] = Akv; gb.A[2] = Akv;
    gb.W[0] = Wq;  gb.W[1] = Wk;  gb.W[2] = Wv;
    gb.bias[0] = bq; gb.bias[1] = bk; gb.bias[2] = bv;
    gb.C[0] = Cq; gb.C[1] = Ck; gb.C[2] = Cv;
    dim3 grid(DD / 128, MM / 128, 3);
    gemm_cp_kernel<<<grid, 256, GEMM_SMEM>>>(gb, MM, DD, DD, 0, 1);
}

extern "C" void kernel_launch(void* const* d_in, const int* in_sizes, int n_in,
                              void* d_out, int out_size)
{
    (void)in_sizes; (void)n_in; (void)out_size;

    const float* enc = (const float*)d_in[0];
    const float* dec = (const float*)d_in[1];
    const float* sa_wq = (const float*)d_in[2];
    const float* sa_bq = (const float*)d_in[3];
    const float* sa_wk = (const float*)d_in[4];
    const float* sa_bk = (const float*)d_in[5];
    const float* sa_wv = (const float*)d_in[6];
    const float* sa_bv = (const float*)d_in[7];
    const float* sa_wo = (const float*)d_in[8];
    const float* sa_bo = (const float*)d_in[9];
    const float* sa_g  = (const float*)d_in[10];
    const float* sa_bt = (const float*)d_in[11];
    const float* ca_wq = (const float*)d_in[12];
    const float* ca_bq = (const float*)d_in[13];
    const float* ca_wk = (const float*)d_in[14];
    const float* ca_bk = (const float*)d_in[15];
    const float* ca_wv = (const float*)d_in[16];
    const float* ca_bv = (const float*)d_in[17];
    const float* ca_wo = (const float*)d_in[18];
    const float* ca_bo = (const float*)d_in[19];
    const float* ca_g  = (const float*)d_in[20];
    const float* ca_bt = (const float*)d_in[21];
    const float* f_w1 = (const float*)d_in[22];
    const float* f_b1 = (const float*)d_in[23];
    const float* f_w2 = (const float*)d_in[24];
    const float* f_b2 = (const float*)d_in[25];
    const float* f_g  = (const float*)d_in[26];
    const float* f_bt = (const float*)d_in[27];

    float* out = (float*)d_out;

    void *pq, *pk, *pv, *pa, *pt, *px, *py, *ph, *pwt, *pdr, *per, *pxr, *pyr;
    cudaGetSymbolAddress(&pq, g_q);
    cudaGetSymbolAddress(&pk, g_k);
    cudaGetSymbolAddress(&pv, g_v);
    cudaGetSymbolAddress(&pa, g_a);
    cudaGetSymbolAddress(&pt, g_t);
    cudaGetSymbolAddress(&px, g_x);
    cudaGetSymbolAddress(&py, g_y);
    cudaGetSymbolAddress(&ph, g_h);
    cudaGetSymbolAddress(&pwt, g_wt);
    cudaGetSymbolAddress(&pdr, g_dr);
    cudaGetSymbolAddress(&per, g_er);
    cudaGetSymbolAddress(&pxr, g_xr);
    cudaGetSymbolAddress(&pyr, g_yr);
    float* q = (float*)pq; float* k = (float*)pk; float* v = (float*)pv;
    float* a = (float*)pa; float* t = (float*)pt; float* x = (float*)px;
    float* y = (float*)py; float* h = (float*)ph;
    float* wt = (float*)pwt;
    float* dr = (float*)pdr; float* er = (float*)per;
    float* xr = (float*)pxr; float* yr = (float*)pyr;

    cudaFuncSetAttribute(attn_mma_kernel,
                         cudaFuncAttributeMaxDynamicSharedMemorySize, ATTN_SMEM);
    cudaFuncSetAttribute(gemm_cp_kernel,
                         cudaFuncAttributeMaxDynamicSharedMemorySize, GEMM_SMEM);

    // rounded weight slices in g_wt (units of 1M floats)
    const size_t U = (size_t)1024 * 1024;
    float* w_sa_q = wt + 0 * U;
    float* w_sa_k = wt + 1 * U;
    float* w_sa_v = wt + 2 * U;
    float* w_sa_o = wt + 3 * U;
    float* w_ca_q = wt + 4 * U;
    float* w_ca_k = wt + 5 * U;
    float* w_ca_v = wt + 6 * U;
    float* w_ca_o = wt + 7 * U;
    float* w_f1   = wt + 8 * U;    // 4M floats
    float* w_f2   = wt + 12 * U;   // 4M floats

    // one fused pre-round launch: 10 weights + dec + enc
    {
        RoundJobs rj;
        const float* srcs[NSEG] = { sa_wq, sa_wk, sa_wv, sa_wo,
                                    ca_wq, ca_wk, ca_wv, ca_wo,
                                    f_w1, f_w2, dec, enc };
        float* dsts[NSEG] = { w_sa_q, w_sa_k, w_sa_v, w_sa_o,
                              w_ca_q, w_ca_k, w_ca_v, w_ca_o,
                              w_f1, w_f2, dr, er };
        int n4s[NSEG] = { 262144, 262144, 262144, 262144,
                          262144, 262144, 262144, 262144,
                          1048576, 1048576, 1048576, 1048576 };
        for (int i = 0; i < NSEG; i++) {
            rj.src[i] = srcs[i]; rj.dst[i] = dsts[i]; rj.n4[i] = n4s[i];
        }
        dim3 rg(4096, NSEG);
        round_all_kernel<<<rg, 256>>>(rj);
    }

    dim3 agrid(SS / AQ, HH, BB);

    // ---- self attention (causal) ----
    launch_gemm_qkv(dr, dr, w_sa_q, w_sa_k, w_sa_v, sa_bq, sa_bk, sa_bv, q, k, v);
    attn_mma_kernel<<<agrid, 128, ATTN_SMEM>>>(q, k, v, a, 1);
    launch_gemm1(a, w_sa_o, sa_bo, t, MM, DD, DD, 0, 0);
    add_ln_kernel<<<MM, 256>>>(t, dec, sa_g, sa_bt, x, xr);

    // ---- cross attention (non-causal) ----
    launch_gemm_qkv(xr, er, w_ca_q, w_ca_k, w_ca_v, ca_bq, ca_bk, ca_bv, q, k, v);
    attn_mma_kernel<<<agrid, 128, ATTN_SMEM>>>(q, k, v, a, 0);
    launch_gemm1(a, w_ca_o, ca_bo, t, MM, DD, DD, 0, 0);
    add_ln_kernel<<<MM, 256>>>(t, x, ca_g, ca_bt, y, yr);

    // ---- FFN ----
    launch_gemm1(yr, w_f1, f_b1, h, MM, FF, DD, 1, 1);
    launch_gemm1(h, w_f2, f_b2, t, MM, DD, FF, 0, 0);
    add_ln_kernel<<<MM, 256>>>(t, y, f_g, f_bt, out, (float*)nullptr);
}

// round 16
// speedup vs baseline: 1.0344x; 1.0063x over previous
#include <cuda_runtime.h>
#include <cuda_bf16.h>
#include <math.h>
#include <stdint.h>

// Problem constants
#define BB 2
#define SS 2048
#define DD 1024
#define HH 16
#define DHH 64
#define FF 4096
#define MM (BB * SS)   // 4096 rows total

// ---------------------------------------------------------------------------
// Scratch buffers (__device__ globals; no allocation allowed)
// ---------------------------------------------------------------------------
__device__ float g_q[(size_t)MM * DD];
__device__ float g_k[(size_t)MM * DD];
__device__ float g_v[(size_t)MM * DD];
__device__ float g_a[(size_t)MM * DD];
__device__ float g_t[(size_t)MM * DD];
__device__ float g_x[(size_t)MM * DD];
__device__ float g_y[(size_t)MM * DD];
__device__ float g_h[(size_t)MM * FF];
__device__ float g_wt[(size_t)16 * 1024 * 1024];  // all rounded weights (64MB)
__device__ float g_dr[(size_t)MM * DD];   // rounded decoder input
__device__ float g_er[(size_t)MM * DD];   // rounded encoder output
__device__ float g_xr[(size_t)MM * DD];   // rounded x
__device__ float g_yr[(size_t)MM * DD];   // rounded y

// ---------------------------------------------------------------------------
// Helpers
// ---------------------------------------------------------------------------
__device__ __forceinline__ uint32_t f2tf32(float x)
{
    uint32_t r;
    asm("cvt.rna.tf32.f32 %0, %1;" : "=r"(r) : "f"(x));
    return r;
}

__device__ __forceinline__ float tf32r(float x)
{
    return __uint_as_float(f2tf32(x));
}

__device__ __forceinline__ uint32_t smem_u32(const void* p)
{
    uint32_t a;
    asm("{ .reg .u64 t; cvta.to.shared.u64 t, %1; cvt.u32.u64 %0, t; }"
        : "=r"(a) : "l"(p));
    return a;
}

__device__ __forceinline__ void cp16(uint32_t dst, const void* src)
{
    asm volatile("cp.async.cg.shared.global [%0], [%1], 16;"
                 :: "r"(dst), "l"(src));
}

#define CP_COMMIT()  asm volatile("cp.async.commit_group;" ::: "memory")
#define CP_WAIT(n)   asm volatile("cp.async.wait_group %0;" :: "n"(n) : "memory")

__device__ __forceinline__ void mma_tf32(float* c, const uint32_t* a, const uint32_t* b)
{
    asm volatile(
        "mma.sync.aligned.m16n8k8.row.col.f32.tf32.tf32.f32 "
        "{%0,%1,%2,%3}, {%4,%5,%6,%7}, {%8,%9}, {%0,%1,%2,%3};"
        : "+f"(c[0]), "+f"(c[1]), "+f"(c[2]), "+f"(c[3])
        : "r"(a[0]), "r"(a[1]), "r"(a[2]), "r"(a[3]), "r"(b[0]), "r"(b[1]));
}

// ---------------------------------------------------------------------------
// TF32 GEMM, cp.async 4-stage pipeline (exact round-7/12 shape).
// C[M,N] = A[M,K] @ W[K,N] + bias[N]; operands pre-rounded tf32.
// 128x128 CTA tile, BK=16, 256 threads (8 warps 2x4), warp tile 64x32.
// As: [4][128][20] floats, Bs: [4][16][136] floats.
// ---------------------------------------------------------------------------
#define ASTR 20
#define BSTR 136
#define AWORDS (128 * ASTR)
#define BWORDS (16 * BSTR)
#define BBASE_W (4 * AWORDS)
#define GEMM_SMEM ((4 * AWORDS + 4 * BWORDS) * 4)

__global__ __launch_bounds__(256)
void gemm_cp_kernel(const float* __restrict__ A, const float* __restrict__ W,
                    const float* __restrict__ bias, float* __restrict__ C,
                    int M, int N, int K, int relu, int rnd)
{
    extern __shared__ float sm[];
    const uint32_t sb = smem_u32(sm);
    const uint32_t* smu = (const uint32_t*)sm;

    const int tid  = threadIdx.x;
    const int warp = tid >> 5;
    const int lane = tid & 31;
    const int wm   = warp >> 2;       // 0..1
    const int wn   = warp & 3;        // 0..3
    const int gid  = lane >> 2;       // 0..7
    const int tig  = lane & 3;        // 0..3

    const int bm = blockIdx.y * 128;
    const int bn = blockIdx.x * 128;

    const int a_row = tid >> 2;       // 0..63 (+64)
    const int a_c4  = tid & 3;
    const int b_row = tid >> 5;       // 0..7 (+8)
    const int b_c4  = tid & 31;

    const float* Ag = A + (size_t)(bm + a_row) * K + a_c4 * 4;
    const float* Wg = W + (size_t)b_row * N + bn + b_c4 * 4;

    const uint32_t aoff0 = (uint32_t)((a_row * ASTR + a_c4 * 4) * 4);
    const uint32_t aoff1 = (uint32_t)(((a_row + 64) * ASTR + a_c4 * 4) * 4);
    const uint32_t boff0 = (uint32_t)((BBASE_W + b_row * BSTR + b_c4 * 4) * 4);
    const uint32_t boff1 = (uint32_t)((BBASE_W + (b_row + 8) * BSTR + b_c4 * 4) * 4);

    float acc[4][4][4];
#pragma unroll
    for (int i = 0; i < 4; i++)
#pragma unroll
        for (int j = 0; j < 4; j++)
#pragma unroll
            for (int r = 0; r < 4; r++) acc[i][j][r] = 0.f;

    const int T = K >> 4;

    // prologue: stages 0..2
#pragma unroll
    for (int s = 0; s < 3; s++) {
        const int k0 = s * 16;
        const uint32_t sa = sb + (uint32_t)(s * AWORDS * 4);
        const uint32_t sbb = sb + (uint32_t)(s * BWORDS * 4);
        cp16(sa + aoff0, Ag + k0);
        cp16(sa + aoff1, Ag + (size_t)64 * K + k0);
        cp16(sbb + boff0, Wg + (size_t)k0 * N);
        cp16(sbb + boff1, Wg + (size_t)(k0 + 8) * N);
        CP_COMMIT();
    }

    for (int it = 0; it < T; it++) {
        CP_WAIT(2);
        __syncthreads();

        const int st = it & 3;
        const uint32_t aw = st * AWORDS;
        const uint32_t bw = BBASE_W + st * BWORDS;

#pragma unroll
        for (int kk = 0; kk < 2; kk++) {
            uint32_t af[4][4], bf[4][2];
            const int kb = kk * 8;
#pragma unroll
            for (int mt = 0; mt < 4; mt++) {
                int mrow = wm * 64 + mt * 16;
                af[mt][0] = smu[aw + (mrow + gid) * ASTR + kb + tig];
                af[mt][1] = smu[aw + (mrow + gid + 8) * ASTR + kb + tig];
                af[mt][2] = smu[aw + (mrow + gid) * ASTR + kb + tig + 4];
                af[mt][3] = smu[aw + (mrow + gid + 8) * ASTR + kb + tig + 4];
            }
#pragma unroll
            for (int nt = 0; nt < 4; nt++) {
                int ncol = wn * 32 + nt * 8;
                bf[nt][0] = smu[bw + (kb + tig) * BSTR + ncol + gid];
                bf[nt][1] = smu[bw + (kb + tig + 4) * BSTR + ncol + gid];
            }
#pragma unroll
            for (int mt = 0; mt < 4; mt++)
#pragma unroll
                for (int nt = 0; nt < 4; nt++)
                    mma_tf32(acc[mt][nt], af[mt], bf[nt]);
        }

        if (it + 3 < T) {
            const int ns = (it + 3) & 3;
            const int k0 = (it + 3) * 16;
            const uint32_t sa = sb + (uint32_t)(ns * AWORDS * 4);
            const uint32_t sbb = sb + (uint32_t)(ns * BWORDS * 4);
            cp16(sa + aoff0, Ag + k0);
            cp16(sa + aoff1, Ag + (size_t)64 * K + k0);
            cp16(sbb + boff0, Wg + (size_t)k0 * N);
            cp16(sbb + boff1, Wg + (size_t)(k0 + 8) * N);
        }
        CP_COMMIT();
    }

    // epilogue
#pragma unroll
    for (int mt = 0; mt < 4; mt++) {
        int row0 = bm + wm * 64 + mt * 16 + gid;
#pragma unroll
        for (int nt = 0; nt < 4; nt++) {
            int col = bn + wn * 32 + nt * 8 + tig * 2;
            float b0 = bias[col], b1 = bias[col + 1];
            float v0 = acc[mt][nt][0] + b0;
            float v1 = acc[mt][nt][1] + b1;
            float v2 = acc[mt][nt][2] + b0;
            float v3 = acc[mt][nt][3] + b1;
            if (relu) {
                v0 = fmaxf(v0, 0.f); v1 = fmaxf(v1, 0.f);
                v2 = fmaxf(v2, 0.f); v3 = fmaxf(v3, 0.f);
            }
            if (rnd) {
                v0 = tf32r(v0); v1 = tf32r(v1);
                v2 = tf32r(v2); v3 = tf32r(v3);
            }
            *(float2*)&C[(size_t)row0 * N + col]       = make_float2(v0, v1);
            *(float2*)&C[(size_t)(row0 + 8) * N + col] = make_float2(v2, v3);
        }
    }
}

// ---------------------------------------------------------------------------
// Batched RNA-round: 12 segments in one launch (grid.y = segment)
// ---------------------------------------------------------------------------
#define NSEG 12
struct RoundJobs {
    const float* src[NSEG];
    float*       dst[NSEG];
    int          n4[NSEG];
};

__global__ __launch_bounds__(256)
void round_all_kernel(RoundJobs rj)
{
    const int seg = blockIdx.y;
    const int i = blockIdx.x * 256 + threadIdx.x;
    if (i < rj.n4[seg]) {
        float4 v = ((const float4*)rj.src[seg])[i];
        ((float4*)rj.dst[seg])[i] =
            make_float4(tf32r(v.x), tf32r(v.y), tf32r(v.z), tf32r(v.w));
    }
}

// ---------------------------------------------------------------------------
// TF32 mma.sync flash attention, cp.async double-buffered K/V
// (exact round-7/12 shape). Block: 128 threads, 64 queries x one head.
// Causal: heavy-first block scheduling (qt reversed) to kill the
// triangular-straggler tail wave.
// ---------------------------------------------------------------------------
#define AQ 64
#define AK 64
#define AST 68
#define KVW (AK * AST)
#define VBASE_W (2 * KVW)
#define PBASE_W (4 * KVW)
#define ATTN_SMEM ((4 * KVW + AQ * AST) * 4)

__global__ __launch_bounds__(128)
void attn_mma_kernel(const float* __restrict__ Q, const float* __restrict__ K,
                     const float* __restrict__ V, float* __restrict__ O,
                     int causal)
{
    extern __shared__ float sm[];
    const uint32_t sb = smem_u32(sm);
    const uint32_t* smu = (const uint32_t*)sm;
    float* Ps = sm + PBASE_W;

    const int tid  = threadIdx.x;
    const int warp = tid >> 5;
    const int lane = tid & 31;
    const int gid  = lane >> 2;
    const int tig  = lane & 3;

    // heavy-first for causal: highest qt (most K tiles) dispatch first
    const int qt = causal ? ((int)gridDim.x - 1 - (int)blockIdx.x)
                          : (int)blockIdx.x;
    const int h  = blockIdx.y;
    const int b  = blockIdx.z;
    const int qbase = qt * AQ;
    const int mrow  = warp * 16;

    const int kr = tid >> 4;
    const int kc4 = tid & 15;
    const float* Kg = K + ((size_t)b * SS + kr) * DD + h * DHH + kc4 * 4;
    const float* Vg = V + ((size_t)b * SS + kr) * DD + h * DHH + kc4 * 4;
    const uint32_t koff = (uint32_t)((kr * AST + kc4 * 4) * 4);
    const uint32_t voff = (uint32_t)((VBASE_W + kr * AST + kc4 * 4) * 4);

    const int ntiles = causal ? (qt + 1) : (SS / AK);

    // issue tile 0
    {
#pragma unroll
        for (int i = 0; i < 8; i++) {
            cp16(sb + koff + (uint32_t)(i * 8 * AST * 4), Kg + (size_t)(i * 8) * DD);
            cp16(sb + voff + (uint32_t)(i * 8 * AST * 4), Vg + (size_t)(i * 8) * DD);
        }
        CP_COMMIT();
    }

    // stage Q (scaled + RNA rounded)
    const float qscale = 0.125f * 1.44269504f;
#pragma unroll
    for (int i = 0; i < 8; i++) {
        int f = tid + i * 128;
        int r = f >> 4, c4 = f & 15;
        float4 v4 = *(const float4*)&Q[((size_t)b * SS + qbase + r) * DD + h * DHH + c4 * 4];
        uint4 u = make_uint4(f2tf32(v4.x * qscale), f2tf32(v4.y * qscale),
                             f2tf32(v4.z * qscale), f2tf32(v4.w * qscale));
        *(uint4*)&Ps[r * AST + c4 * 4] = u;
    }
    __syncthreads();

    uint32_t qf[8][4];
#pragma unroll
    for (int ks = 0; ks < 8; ks++) {
        qf[ks][0] = smu[PBASE_W + (mrow + gid) * AST + ks * 8 + tig];
        qf[ks][1] = smu[PBASE_W + (mrow + gid + 8) * AST + ks * 8 + tig];
        qf[ks][2] = smu[PBASE_W + (mrow + gid) * AST + ks * 8 + tig + 4];
        qf[ks][3] = smu[PBASE_W + (mrow + gid + 8) * AST + ks * 8 + tig + 4];
    }

    float oacc[8][4];
#pragma unroll
    for (int nt = 0; nt < 8; nt++)
#pragma unroll
        for (int r = 0; r < 4; r++) oacc[nt][r] = 0.f;
    float m0 = -1e30f, m1 = -1e30f, l0 = 0.f, l1 = 0.f;

    for (int t = 0; t < ntiles; t++) {
        if (t + 1 < ntiles) {
            const int ns = (t + 1) & 1;
            const uint32_t kd = sb + koff + (uint32_t)(ns * KVW * 4);
            const uint32_t vd = sb + voff + (uint32_t)(ns * KVW * 4);
            const float* Kp = Kg + (size_t)(t + 1) * AK * DD;
            const float* Vp = Vg + (size_t)(t + 1) * AK * DD;
#pragma unroll
            for (int i = 0; i < 8; i++) {
                cp16(kd + (uint32_t)(i * 8 * AST * 4), Kp + (size_t)(i * 8) * DD);
                cp16(vd + (uint32_t)(i * 8 * AST * 4), Vp + (size_t)(i * 8) * DD);
            }
            CP_COMMIT();
            CP_WAIT(1);
        } else {
            CP_WAIT(0);
        }
        __syncthreads();

        const uint32_t kw = (t & 1) * KVW;
        const uint32_t vw = VBASE_W + (t & 1) * KVW;
        const int k0 = t * AK;

        float sacc[8][4];
#pragma unroll
        for (int nt = 0; nt < 8; nt++)
#pragma unroll
            for (int r = 0; r < 4; r++) sacc[nt][r] = 0.f;

#pragma unroll
        for (int ks = 0; ks < 8; ks++) {
            uint32_t bf[8][2];
            const int d0 = ks * 8 + tig;
#pragma unroll
            for (int nt = 0; nt < 8; nt++) {
                const uint32_t krow = kw + (nt * 8 + gid) * AST;
                bf[nt][0] = smu[krow + d0];
                bf[nt][1] = smu[krow + d0 + 4];
            }
#pragma unroll
            for (int nt = 0; nt < 8; nt++)
                mma_tf32(sacc[nt], qf[ks], bf[nt]);
        }

        if (causal && t == qt) {
            int q0 = qbase + mrow + gid;
            int q1 = q0 + 8;
#pragma unroll
            for (int nt = 0; nt < 8; nt++) {
                int key = k0 + nt * 8 + tig * 2;
                if (key > q0)     sacc[nt][0] = -1e30f;
                if (key + 1 > q0) sacc[nt][1] = -1e30f;
                if (key > q1)     sacc[nt][2] = -1e30f;
                if (key + 1 > q1) sacc[nt][3] = -1e30f;
            }
        }

        float mx0 = -1e30f, mx1 = -1e30f;
#pragma unroll
        for (int nt = 0; nt < 8; nt++) {
            mx0 = fmaxf(mx0, fmaxf(sacc[nt][0], sacc[nt][1]));
            mx1 = fmaxf(mx1, fmaxf(sacc[nt][2], sacc[nt][3]));
        }
        mx0 = fmaxf(mx0, __shfl_xor_sync(0xffffffffu, mx0, 1));
        mx0 = fmaxf(mx0, __shfl_xor_sync(0xffffffffu, mx0, 2));
        mx1 = fmaxf(mx1, __shfl_xor_sync(0xffffffffu, mx1, 1));
        mx1 = fmaxf(mx1, __shfl_xor_sync(0xffffffffu, mx1, 2));

        float nm0 = fmaxf(m0, mx0), nm1 = fmaxf(m1, mx1);
        float c0 = exp2f(m0 - nm0), c1 = exp2f(m1 - nm1);
        m0 = nm0; m1 = nm1;

        float rs0 = 0.f, rs1 = 0.f;
#pragma unroll
        for (int nt = 0; nt < 8; nt++) {
            float p0 = exp2f(sacc[nt][0] - m0);
            float p1 = exp2f(sacc[nt][1] - m0);
            float p2 = exp2f(sacc[nt][2] - m1);
            float p3 = exp2f(sacc[nt][3] - m1);
            rs0 += p0 + p1;
            rs1 += p2 + p3;
            oacc[nt][0] *= c0; oacc[nt][1] *= c0;
            oacc[nt][2] *= c1; oacc[nt][3] *= c1;
            uint2 u01 = make_uint2(f2tf32(p0), f2tf32(p1));
            uint2 u23 = make_uint2(f2tf32(p2), f2tf32(p3));
            *(uint2*)&Ps[(mrow + gid) * AST + nt * 8 + tig * 2]     = u01;
            *(uint2*)&Ps[(mrow + gid + 8) * AST + nt * 8 + tig * 2] = u23;
        }
        rs0 += __shfl_xor_sync(0xffffffffu, rs0, 1);
        rs0 += __shfl_xor_sync(0xffffffffu, rs0, 2);
        rs1 += __shfl_xor_sync(0xffffffffu, rs1, 1);
        rs1 += __shfl_xor_sync(0xffffffffu, rs1, 2);
        l0 = l0 * c0 + rs0;
        l1 = l1 * c1 + rs1;
        __syncwarp();

#pragma unroll
        for (int ks = 0; ks < 8; ks++) {
            uint32_t af[4];
            af[0] = smu[PBASE_W + (mrow + gid) * AST + ks * 8 + tig];
            af[1] = smu[PBASE_W + (mrow + gid + 8) * AST + ks * 8 + tig];
            af[2] = smu[PBASE_W + (mrow + gid) * AST + ks * 8 + tig + 4];
            af[3] = smu[PBASE_W + (mrow + gid + 8) * AST + ks * 8 + tig + 4];
            uint32_t bf[8][2];
            const uint32_t vr0 = vw + (ks * 8 + tig) * AST;
            const uint32_t vr1 = vw + (ks * 8 + tig + 4) * AST;
#pragma unroll
            for (int nt = 0; nt < 8; nt++) {
                bf[nt][0] = smu[vr0 + nt * 8 + gid];
                bf[nt][1] = smu[vr1 + nt * 8 + gid];
            }
#pragma unroll
            for (int nt = 0; nt < 8; nt++)
                mma_tf32(oacc[nt], af, bf[nt]);
        }
        __syncthreads();
    }

    float inv0 = 1.f / l0, inv1 = 1.f / l1;
    int row0 = qbase + mrow + gid;
#pragma unroll
    for (int nt = 0; nt < 8; nt++) {
        int col = h * DHH + nt * 8 + tig * 2;
        *(float2*)&O[((size_t)b * SS + row0) * DD + col] =
            make_float2(tf32r(oacc[nt][0] * inv0), tf32r(oacc[nt][1] * inv0));
        *(float2*)&O[((size_t)b * SS + row0 + 8) * DD + col] =
            make_float2(tf32r(oacc[nt][2] * inv1), tf32r(oacc[nt][3] * inv1));
    }
}

// ---------------------------------------------------------------------------
// out = LayerNorm(a + res) * g + bt ; optional second rounded output
// ---------------------------------------------------------------------------
__inline__ __device__ float warp_sum(float v)
{
#pragma unroll
    for (int o = 16; o > 0; o >>= 1) v += __shfl_xor_sync(0xffffffffu, v, o);
    return v;
}

__global__ __launch_bounds__(256)
void add_ln_kernel(const float* __restrict__ a, const float* __restrict__ res,
                   const float* __restrict__ g, const float* __restrict__ bt,
                   float* __restrict__ out, float* __restrict__ out_r)
{
    __shared__ float buf[DD];
    __shared__ float red1[8], red2[8];

    const size_t row = blockIdx.x;
    const float* ap = a + row * DD;
    const float* rp = res + row * DD;

    float sum = 0.f, sq = 0.f;
    for (int i = threadIdx.x; i < DD; i += 256) {
        float v = ap[i] + rp[i];
        buf[i] = v;
        sum += v;
        sq  = fmaf(v, v, sq);
    }
    sum = warp_sum(sum);
    sq  = warp_sum(sq);
    int warp = threadIdx.x >> 5, lane = threadIdx.x & 31;
    if (lane == 0) { red1[warp] = sum; red2[warp] = sq; }
    __syncthreads();
    if (warp == 0) {
        float s1 = lane < 8 ? red1[lane] : 0.f;
        float s2 = lane < 8 ? red2[lane] : 0.f;
        s1 = warp_sum(s1);
        s2 = warp_sum(s2);
        if (lane == 0) { red1[0] = s1; red2[0] = s2; }
    }
    __syncthreads();
    float mu  = red1[0] * (1.f / DD);
    float var = red2[0] * (1.f / DD) - mu * mu;
    float rstd = rsqrtf(var + 1e-5f);

    for (int i = threadIdx.x; i < DD; i += 256) {
        float v = (buf[i] - mu) * rstd * g[i] + bt[i];
        out[row * DD + i] = v;
        if (out_r) out_r[row * DD + i] = tf32r(v);
    }
}

// ---------------------------------------------------------------------------
// Host orchestration
// ---------------------------------------------------------------------------
static void launch_gemm(const float* A, const float* W, const float* bias,
                        float* C, int M, int N, int K, int relu, int rnd)
{
    dim3 grid(N / 128, M / 128);
    gemm_cp_kernel<<<grid, 256, GEMM_SMEM>>>(A, W, bias, C, M, N, K, relu, rnd);
}

extern "C" void kernel_launch(void* const* d_in, const int* in_sizes, int n_in,
                              void* d_out, int out_size)
{
    (void)in_sizes; (void)n_in; (void)out_size;

    const float* enc = (const float*)d_in[0];
    const float* dec = (const float*)d_in[1];
    const float* sa_wq = (const float*)d_in[2];
    const float* sa_bq = (const float*)d_in[3];
    const float* sa_wk = (const float*)d_in[4];
    const float* sa_bk = (const float*)d_in[5];
    const float* sa_wv = (const float*)d_in[6];
    const float* sa_bv = (const float*)d_in[7];
    const float* sa_wo = (const float*)d_in[8];
    const float* sa_bo = (const float*)d_in[9];
    const float* sa_g  = (const float*)d_in[10];
    const float* sa_bt = (const float*)d_in[11];
    const float* ca_wq = (const float*)d_in[12];
    const float* ca_bq = (const float*)d_in[13];
    const float* ca_wk = (const float*)d_in[14];
    const float* ca_bk = (const float*)d_in[15];
    const float* ca_wv = (const float*)d_in[16];
    const float* ca_bv = (const float*)d_in[17];
    const float* ca_wo = (const float*)d_in[18];
    const float* ca_bo = (const float*)d_in[19];
    const float* ca_g  = (const float*)d_in[20];
    const float* ca_bt = (const float*)d_in[21];
    const float* f_w1 = (const float*)d_in[22];
    const float* f_b1 = (const float*)d_in[23];
    const float* f_w2 = (const float*)d_in[24];
    const float* f_b2 = (const float*)d_in[25];
    const float* f_g  = (const float*)d_in[26];
    const float* f_bt = (const float*)d_in[27];

    float* out = (float*)d_out;

    void *pq, *pk, *pv, *pa, *pt, *px, *py, *ph, *pwt, *pdr, *per, *pxr, *pyr;
    cudaGetSymbolAddress(&pq, g_q);
    cudaGetSymbolAddress(&pk, g_k);
    cudaGetSymbolAddress(&pv, g_v);
    cudaGetSymbolAddress(&pa, g_a);
    cudaGetSymbolAddress(&pt, g_t);
    cudaGetSymbolAddress(&px, g_x);
    cudaGetSymbolAddress(&py, g_y);
    cudaGetSymbolAddress(&ph, g_h);
    cudaGetSymbolAddress(&pwt, g_wt);
    cudaGetSymbolAddress(&pdr, g_dr);
    cudaGetSymbolAddress(&per, g_er);
    cudaGetSymbolAddress(&pxr, g_xr);
    cudaGetSymbolAddress(&pyr, g_yr);
    float* q = (float*)pq; float* k = (float*)pk; float* v = (float*)pv;
    float* a = (float*)pa; float* t = (float*)pt; float* x = (float*)px;
    float* y = (float*)py; float* h = (float*)ph;
    float* wt = (float*)pwt;
    float* dr = (float*)pdr; float* er = (float*)per;
    float* xr = (float*)pxr; float* yr = (float*)pyr;

    cudaFuncSetAttribute(attn_mma_kernel,
                         cudaFuncAttributeMaxDynamicSharedMemorySize, ATTN_SMEM);
    cudaFuncSetAttribute(gemm_cp_kernel,
                         cudaFuncAttributeMaxDynamicSharedMemorySize, GEMM_SMEM);

    // rounded weight slices in g_wt (units of 1M floats)
    const size_t U = (size_t)1024 * 1024;
    float* w_sa_q = wt + 0 * U;
    float* w_sa_k = wt + 1 * U;
    float* w_sa_v = wt + 2 * U;
    float* w_sa_o = wt + 3 * U;
    float* w_ca_q = wt + 4 * U;
    float* w_ca_k = wt + 5 * U;
    float* w_ca_v = wt + 6 * U;
    float* w_ca_o = wt + 7 * U;
    float* w_f1   = wt + 8 * U;    // 4M floats
    float* w_f2   = wt + 12 * U;   // 4M floats

    // one fused pre-round launch: 10 weights + dec + enc
    {
        RoundJobs rj;
        const float* srcs[NSEG] = { sa_wq, sa_wk, sa_wv, sa_wo,
                                    ca_wq, ca_wk, ca_wv, ca_wo,
                                    f_w1, f_w2, dec, enc };
        float* dsts[NSEG] = { w_sa_q, w_sa_k, w_sa_v, w_sa_o,
                              w_ca_q, w_ca_k, w_ca_v, w_ca_o,
                              w_f1, w_f2, dr, er };
        int n4s[NSEG] = { 262144, 262144, 262144, 262144,
                          262144, 262144, 262144, 262144,
                          1048576, 1048576, 1048576, 1048576 };
        for (int i = 0; i < NSEG; i++) {
            rj.src[i] = srcs[i]; rj.dst[i] = dsts[i]; rj.n4[i] = n4s[i];
        }
        dim3 rg(4096, NSEG);
        round_all_kernel<<<rg, 256>>>(rj);
    }

    dim3 agrid(SS / AQ, HH, BB);

    // ---- self attention (causal) ----
    launch_gemm(dr, w_sa_q, sa_bq, q, MM, DD, DD, 0, 1);
    launch_gemm(dr, w_sa_k, sa_bk, k, MM, DD, DD, 0, 1);
    launch_gemm(dr, w_sa_v, sa_bv, v, MM, DD, DD, 0, 1);
    attn_mma_kernel<<<agrid, 128, ATTN_SMEM>>>(q, k, v, a, 1);
    launch_gemm(a, w_sa_o, sa_bo, t, MM, DD, DD, 0, 0);
    add_ln_kernel<<<MM, 256>>>(t, dec, sa_g, sa_bt, x, xr);

    // ---- cross attention (non-causal) ----
    launch_gemm(xr, w_ca_q, ca_bq, q, MM, DD, DD, 0, 1);
    launch_gemm(er, w_ca_k, ca_bk, k, MM, DD, DD, 0, 1);
    launch_gemm(er, w_ca_v, ca_bv, v, MM, DD, DD, 0, 1);
    attn_mma_kernel<<<agrid, 128, ATTN_SMEM>>>(q, k, v, a, 0);
    launch_gemm(a, w_ca_o, ca_bo, t, MM, DD, DD, 0, 0);
    add_ln_kernel<<<MM, 256>>>(t, x, ca_g, ca_bt, y, yr);

    // ---- FFN ----
    launch_gemm(yr, w_f1, f_b1, h, MM, FF, DD, 1, 1);
    launch_gemm(h, w_f2, f_b2, t, MM, DD, FF, 0, 0);
    add_ln_kernel<<<MM, 256>>>(t, y, f_g, f_bt, out, (float*)nullptr);
}